// round 4
// baseline (speedup 1.0000x reference)
#include <cuda_runtime.h>
#include <math.h>

#define NBATCH 8
#define NPTS   8192
#define NCAND  2048
#define NG4    (NCAND / 4)          // 512 groups of 4
#define NG8    (NCAND / 8)          // 256 groups of 8
#define NTHREADS 256
#define PTS_PER_BLOCK NTHREADS      // 1 point per thread
#define NBLK (NPTS / PTS_PER_BLOCK) // 32 blocks per batch

#define BASE_ALPHA 0.05f
#define EPS_F      1e-6f

typedef unsigned long long ull;

// Scratch (allocation-free rule: __device__ globals). Set 1 = iter1, set 2 = iter2.
__device__ float g_md1[NBATCH * NPTS];
__device__ int   g_bi1[NBATCH * NPTS];
__device__ float g_bm1[NBATCH * NBLK];
__device__ float g_md2[NBATCH * NPTS];
__device__ int   g_bi2[NBATCH * NPTS];
__device__ float g_bm2[NBATCH * NBLK];

// ---- packed fp32x2 helpers (sm_100+; ptxas never emits FFMA2 from C++) ----
__device__ __forceinline__ ull ffma2(ull a, ull b, ull c) {
    ull d;
    asm("fma.rn.f32x2 %0, %1, %2, %3;" : "=l"(d) : "l"(a), "l"(b), "l"(c));
    return d;
}
__device__ __forceinline__ ull pack2(float lo, float hi) {
    ull r;
    asm("mov.b64 %0, {%1, %2};" : "=l"(r) : "f"(lo), "f"(hi));
    return r;
}
__device__ __forceinline__ void unpack2(ull v, float& lo, float& hi) {
    asm("mov.b64 {%0, %1}, %2;" : "=f"(lo), "=f"(hi) : "l"(v));
}

__device__ __forceinline__ float batch_max(const float* __restrict__ bm, int b) {
    float m = __ldg(&bm[b * NBLK]);
#pragma unroll
    for (int k = 1; k < NBLK; k++) m = fmaxf(m, __ldg(&bm[b * NBLK + k]));
    return m;
}

// min over 4 candidates stored as (xl,xh)(yl,yh)(zl,zh)(hl,hh) packed pairs.
// score = ax*x + (ay*y + (az*z + h)), ax = -px etc.  (argmin of 0.5*d^2 - 0.5*|p|^2)
__device__ __forceinline__ float min4(ull ax, ull ay, ull az,
                                      ulonglong2 X, ulonglong2 Y,
                                      ulonglong2 Z, ulonglong2 H) {
    ull tl = ffma2(az, Z.x, H.x);
    tl = ffma2(ay, Y.x, tl);
    tl = ffma2(ax, X.x, tl);
    ull th = ffma2(az, Z.y, H.y);
    th = ffma2(ay, Y.y, th);
    th = ffma2(ax, X.y, th);
    float s0, s1, s2, s3;
    unpack2(tl, s0, s1);
    unpack2(th, s2, s3);
    return fminf(fminf(s0, s1), fminf(s2, s3));
}

// Find first j in [0,8) of winning group-of-8 with score <= best.
// sf points at the group's smem floats: [x0..3 y0..3 z0..3 h0..3][x4..7 ...].
// Scalar FMA chain is bitwise-identical to the packed lanes -> exact match exists.
__device__ __forceinline__ int resolve8(const float* __restrict__ sf,
                                        float ax, float ay, float az, float best) {
    int r = 7;
#pragma unroll
    for (int j = 6; j >= 0; j--) {
        const int q = (j >> 2) * 16, l = j & 3;
        float s = fmaf(ax, sf[q + l],
                  fmaf(ay, sf[q + 4 + l],
                  fmaf(az, sf[q + 8 + l], sf[q + 12 + l])));
        if (s <= best) r = j;
    }
    return r;
}

// ITER==1: refined = pred, write set 1.
// ITER==2: refined = update(pred, set 1) computed in the prologue, write set 2.
template <int ITER>
__global__ __launch_bounds__(NTHREADS)
void nearest_kernel(const float* __restrict__ pred,
                    const float* __restrict__ partial) {
    // group-of-4 g: sG[4g+0]=(x0,x1,x2,x3), +1=y, +2=z, +3=h (h=0.5*|c|^2). 32KB.
    __shared__ float4 sG[4 * NG4];
    __shared__ float s_warpmax[NTHREADS / 32];

    const int b = blockIdx.y;
    const float* __restrict__ pp = partial + (size_t)b * NCAND * 3;
    const float4* __restrict__ pp4 = (const float4*)pp;

    // Cooperative transpose load: 3 float4 of AoS -> 4 float4 of SoA per group-of-4.
    for (int g = threadIdx.x; g < NG4; g += NTHREADS) {
        float4 A = pp4[3 * g + 0];   // x0 y0 z0 x1
        float4 B = pp4[3 * g + 1];   // y1 z1 x2 y2
        float4 C = pp4[3 * g + 2];   // z2 x3 y3 z3
        float4 X = make_float4(A.x, A.w, B.z, C.y);
        float4 Y = make_float4(A.y, B.x, B.w, C.z);
        float4 Z = make_float4(A.z, B.y, C.x, C.w);
        float4 H = make_float4(0.5f * (X.x * X.x + Y.x * Y.x + Z.x * Z.x),
                               0.5f * (X.y * X.y + Y.y * Y.y + Z.y * Z.y),
                               0.5f * (X.z * X.z + Y.z * Y.z + Z.z * Z.z),
                               0.5f * (X.w * X.w + Y.w * Y.w + Z.w * Z.w));
        sG[4 * g + 0] = X;
        sG[4 * g + 1] = Y;
        sG[4 * g + 2] = Z;
        sG[4 * g + 3] = H;
    }
    __syncthreads();

    const int p = blockIdx.x * PTS_PER_BLOCK + threadIdx.x;  // batch-local point
    const float* __restrict__ pb = pred + (size_t)b * NPTS * 3;

    float rx = pb[3 * p], ry = pb[3 * p + 1], rz = pb[3 * p + 2];
    if (ITER == 2) {
        const float rbm = 1.0f / (batch_max(g_bm1, b) + EPS_F);
        const int gi = b * NPTS + p;
        const float a = BASE_ALPHA * (2.0f - g_md1[gi] * rbm);
        const float* pc = pp + 3 * g_bi1[gi];
        rx += a * (pc[0] - rx); ry += a * (pc[1] - ry); rz += a * (pc[2] - rz);
    }

    const ull ax = pack2(-rx, -rx), ay = pack2(-ry, -ry), az = pack2(-rz, -rz);

    float best = 3.0e38f;
    int gbest = 0;

    const ulonglong2* __restrict__ su = reinterpret_cast<const ulonglong2*>(sG);

#pragma unroll 2
    for (int g = 0; g < NG8; g++) {
        // two groups-of-4, loaded straight into aligned 64-bit pairs (LDS.128)
        ulonglong2 Xa = su[8 * g + 0], Ya = su[8 * g + 1];
        ulonglong2 Za = su[8 * g + 2], Ha = su[8 * g + 3];
        ulonglong2 Xb = su[8 * g + 4], Yb = su[8 * g + 5];
        ulonglong2 Zb = su[8 * g + 6], Hb = su[8 * g + 7];

        float m = fminf(min4(ax, ay, az, Xa, Ya, Za, Ha),
                        min4(ax, ay, az, Xb, Yb, Zb, Hb));
        if (m < best) { best = m; gbest = g; }   // strict <: first group wins ties
    }

    const float* sf = reinterpret_cast<const float*>(sG);
    const int bi = 8 * gbest + resolve8(sf + 32 * gbest, -rx, -ry, -rz, best);

    const float p2 = rx * rx + ry * ry + rz * rz;
    const float d = sqrtf(fmaxf(fmaf(2.0f, best, p2), 0.0f));

    float* md_out = (ITER == 1) ? g_md1 : g_md2;
    int*   bi_out = (ITER == 1) ? g_bi1 : g_bi2;
    float* bm_out = (ITER == 1) ? g_bm1 : g_bm2;

    md_out[b * NPTS + p] = d;
    bi_out[b * NPTS + p] = bi;

    // Block max (no atomics, no init kernel: every slot written every launch)
    float m = d;
#pragma unroll
    for (int off = 16; off > 0; off >>= 1)
        m = fmaxf(m, __shfl_xor_sync(0xffffffffu, m, off));
    if ((threadIdx.x & 31) == 0) s_warpmax[threadIdx.x >> 5] = m;
    __syncthreads();
    if (threadIdx.x == 0) {
        float mm = s_warpmax[0];
#pragma unroll
        for (int w = 1; w < NTHREADS / 32; w++) mm = fmaxf(mm, s_warpmax[w]);
        bm_out[b * NBLK + blockIdx.x] = mm;
    }
}

// Replays update 1 (pred -> refined1) and update 2 (refined1 -> out).
__global__ void finalize_kernel(const float* __restrict__ pred,
                                const float* __restrict__ partial,
                                float* __restrict__ out) {
    const int i = blockIdx.x * blockDim.x + threadIdx.x;  // global point index
    if (i >= NBATCH * NPTS) return;
    const int b = i / NPTS;
    const float* __restrict__ pp = partial + (size_t)b * NCAND * 3;

    const float rbm1 = 1.0f / (batch_max(g_bm1, b) + EPS_F);
    const float rbm2 = 1.0f / (batch_max(g_bm2, b) + EPS_F);

    float rx = pred[3 * i], ry = pred[3 * i + 1], rz = pred[3 * i + 2];
    {
        float a = BASE_ALPHA * (2.0f - g_md1[i] * rbm1);
        const float* pc = pp + 3 * g_bi1[i];
        rx += a * (pc[0] - rx); ry += a * (pc[1] - ry); rz += a * (pc[2] - rz);
    }
    {
        float a = BASE_ALPHA * (2.0f - g_md2[i] * rbm2);
        const float* pc = pp + 3 * g_bi2[i];
        rx += a * (pc[0] - rx); ry += a * (pc[1] - ry); rz += a * (pc[2] - rz);
    }
    out[3 * i + 0] = rx;
    out[3 * i + 1] = ry;
    out[3 * i + 2] = rz;
}

extern "C" void kernel_launch(void* const* d_in, const int* in_sizes, int n_in,
                              void* d_out, int out_size) {
    const float* pred    = (const float*)d_in[0];   // [8,8192,3]
    const float* partial = (const float*)d_in[1];   // [8,2048,3]
    float* out = (float*)d_out;                     // [8,8192,3]

    const dim3 grid(NBLK, NBATCH);                  // 256 blocks, ~2 blocks/SM
    const int tot = NBATCH * NPTS;

    nearest_kernel<1><<<grid, NTHREADS>>>(pred, partial);
    nearest_kernel<2><<<grid, NTHREADS>>>(pred, partial);
    finalize_kernel<<<(tot + 255) / 256, 256>>>(pred, partial, out);
}

// round 6
// speedup vs baseline: 1.1976x; 1.1976x over previous
#include <cuda_runtime.h>
#include <math.h>

#define NBATCH 8
#define NPTS   8192
#define NCAND  2048
#define NHALF  2
#define NCH    (NCAND / NHALF)      // 1024 candidates per half
#define NG4H   (NCH / 4)            // 256 groups of 4 per half
#define NG8H   (NCH / 8)            // 128 groups of 8 per half
#define NTHREADS 256
#define PTS_PER_BLOCK 512           // 2 points per thread
#define HBLK (NPTS / PTS_PER_BLOCK) // 16 point-blocks per batch per half
#define MBLK (NPTS / NTHREADS)      // 32 merge blocks per batch

#define BASE_ALPHA 0.05f
#define EPS_F      1e-6f

typedef unsigned long long ull;

// Scratch (allocation-free rule: __device__ globals).
__device__ ull   g_key1[NHALF * NBATCH * NPTS];
__device__ ull   g_key2[NHALF * NBATCH * NPTS];
__device__ float g_p21[NBATCH * NPTS];
__device__ float g_p22[NBATCH * NPTS];
__device__ float g_md1[NBATCH * NPTS];
__device__ int   g_bi1[NBATCH * NPTS];
__device__ float g_bm1[NBATCH * MBLK];
__device__ float g_md2[NBATCH * NPTS];
__device__ int   g_bi2[NBATCH * NPTS];
__device__ float g_bm2[NBATCH * MBLK];

// ---- packed fp32x2 helpers (sm_100+; ptxas never emits FFMA2 from C++) ----
__device__ __forceinline__ ull ffma2(ull a, ull b, ull c) {
    ull d;
    asm("fma.rn.f32x2 %0, %1, %2, %3;" : "=l"(d) : "l"(a), "l"(b), "l"(c));
    return d;
}
__device__ __forceinline__ ull pack2(float lo, float hi) {
    ull r;
    asm("mov.b64 %0, {%1, %2};" : "=l"(r) : "f"(lo), "f"(hi));
    return r;
}
__device__ __forceinline__ void unpack2(ull v, float& lo, float& hi) {
    asm("mov.b64 {%0, %1}, %2;" : "=f"(lo), "=f"(hi) : "l"(v));
}

// Ordered key: flipped float score (monotonic as unsigned) || candidate index.
// min(key) == min score, ties -> smaller index (jnp.argmin first-occurrence).
__device__ __forceinline__ ull make_key(float s, int idx) {
    unsigned int b = __float_as_uint(s);
    b = (b & 0x80000000u) ? ~b : (b | 0x80000000u);
    return ((ull)b << 32) | (unsigned int)idx;
}
__device__ __forceinline__ float key_score(ull k) {
    unsigned int fb = (unsigned int)(k >> 32);
    unsigned int b = (fb & 0x80000000u) ? (fb ^ 0x80000000u) : ~fb;
    return __uint_as_float(b);
}

__device__ __forceinline__ float batch_max(const float* __restrict__ bm, int b) {
    float m = __ldg(&bm[b * MBLK]);
#pragma unroll
    for (int k = 1; k < MBLK; k++) m = fmaxf(m, __ldg(&bm[b * MBLK + k]));
    return m;
}

// min over 4 candidates stored as (xl,xh)(yl,yh)(zl,zh)(hl,hh) packed pairs.
// score = ax*x + (ay*y + (az*z + h)), ax = -px etc.  (argmin of 0.5*d^2 - 0.5*|p|^2)
__device__ __forceinline__ float min4(ull ax, ull ay, ull az,
                                      ulonglong2 X, ulonglong2 Y,
                                      ulonglong2 Z, ulonglong2 H) {
    ull tl = ffma2(az, Z.x, H.x);
    tl = ffma2(ay, Y.x, tl);
    tl = ffma2(ax, X.x, tl);
    ull th = ffma2(az, Z.y, H.y);
    th = ffma2(ay, Y.y, th);
    th = ffma2(ax, X.y, th);
    float s0, s1, s2, s3;
    unpack2(tl, s0, s1);
    unpack2(th, s2, s3);
    return fminf(fminf(s0, s1), fminf(s2, s3));
}

// First j in [0,8) of winning group-of-8 with score <= best (bitwise-identical
// scalar FMA chain to the packed lanes, so an exact match exists).
__device__ __forceinline__ int resolve8(const float* __restrict__ sf,
                                        float ax, float ay, float az, float best) {
    int r = 7;
#pragma unroll
    for (int j = 6; j >= 0; j--) {
        const int q = (j >> 2) * 16, l = j & 3;
        float s = fmaf(ax, sf[q + l],
                  fmaf(ay, sf[q + 4 + l],
                  fmaf(az, sf[q + 8 + l], sf[q + 12 + l])));
        if (s <= best) r = j;
    }
    return r;
}

// ITER==1: refined = pred. ITER==2: refined = update1(pred) in the prologue.
// Each block scans one candidate HALF for 512 points; writes ordered keys.
template <int ITER>
__global__ __launch_bounds__(NTHREADS)
void nearest_kernel(const float* __restrict__ pred,
                    const float* __restrict__ partial) {
    __shared__ float4 sG[4 * NG4H];   // 16 KB: this half's candidates, SoA-by-4 + h

    const int b    = blockIdx.y;
    const int half = blockIdx.x >> 4;        // 0 or 1
    const int pblk = blockIdx.x & (HBLK - 1);

    const float* __restrict__ ppb = partial + (size_t)b * NCAND * 3;       // full batch
    const float* __restrict__ pp  = ppb + (size_t)half * NCH * 3;          // this half
    const float4* __restrict__ pp4 = (const float4*)pp;

    // Cooperative transpose: 3 float4 AoS -> 4 float4 SoA per group-of-4.
    for (int g = threadIdx.x; g < NG4H; g += NTHREADS) {
        float4 A = pp4[3 * g + 0];   // x0 y0 z0 x1
        float4 B = pp4[3 * g + 1];   // y1 z1 x2 y2
        float4 C = pp4[3 * g + 2];   // z2 x3 y3 z3
        float4 X = make_float4(A.x, A.w, B.z, C.y);
        float4 Y = make_float4(A.y, B.x, B.w, C.z);
        float4 Z = make_float4(A.z, B.y, C.x, C.w);
        float4 H = make_float4(0.5f * (X.x * X.x + Y.x * Y.x + Z.x * Z.x),
                               0.5f * (X.y * X.y + Y.y * Y.y + Z.y * Z.y),
                               0.5f * (X.z * X.z + Y.z * Y.z + Z.z * Z.z),
                               0.5f * (X.w * X.w + Y.w * Y.w + Z.w * Z.w));
        sG[4 * g + 0] = X;
        sG[4 * g + 1] = Y;
        sG[4 * g + 2] = Z;
        sG[4 * g + 3] = H;
    }
    __syncthreads();

    const int p0 = pblk * PTS_PER_BLOCK + threadIdx.x;   // batch-local point
    const int p1 = p0 + NTHREADS;
    const float* __restrict__ pb = pred + (size_t)b * NPTS * 3;

    float rx0 = pb[3 * p0], ry0 = pb[3 * p0 + 1], rz0 = pb[3 * p0 + 2];
    float rx1 = pb[3 * p1], ry1 = pb[3 * p1 + 1], rz1 = pb[3 * p1 + 2];
    if (ITER == 2) {
        const float rbm = 1.0f / (batch_max(g_bm1, b) + EPS_F);
        int gi = b * NPTS + p0;
        float a = BASE_ALPHA * (2.0f - g_md1[gi] * rbm);
        const float* pc = ppb + 3 * g_bi1[gi];
        rx0 += a * (pc[0] - rx0); ry0 += a * (pc[1] - ry0); rz0 += a * (pc[2] - rz0);
        gi = b * NPTS + p1;
        a = BASE_ALPHA * (2.0f - g_md1[gi] * rbm);
        pc = ppb + 3 * g_bi1[gi];
        rx1 += a * (pc[0] - rx1); ry1 += a * (pc[1] - ry1); rz1 += a * (pc[2] - rz1);
    }

    const ull ax0 = pack2(-rx0, -rx0), ay0 = pack2(-ry0, -ry0), az0 = pack2(-rz0, -rz0);
    const ull ax1 = pack2(-rx1, -rx1), ay1 = pack2(-ry1, -ry1), az1 = pack2(-rz1, -rz1);

    float best0 = 3.0e38f, best1 = 3.0e38f;
    int gi0 = 0, gi1 = 0;

    const ulonglong2* __restrict__ su = reinterpret_cast<const ulonglong2*>(sG);

#pragma unroll 2
    for (int g = 0; g < NG8H; g++) {
        ulonglong2 Xa = su[8 * g + 0], Ya = su[8 * g + 1];
        ulonglong2 Za = su[8 * g + 2], Ha = su[8 * g + 3];
        ulonglong2 Xb = su[8 * g + 4], Yb = su[8 * g + 5];
        ulonglong2 Zb = su[8 * g + 6], Hb = su[8 * g + 7];

        float m0 = fminf(min4(ax0, ay0, az0, Xa, Ya, Za, Ha),
                         min4(ax0, ay0, az0, Xb, Yb, Zb, Hb));
        if (m0 < best0) { best0 = m0; gi0 = g; }   // strict <: first group wins ties

        float m1 = fminf(min4(ax1, ay1, az1, Xa, Ya, Za, Ha),
                         min4(ax1, ay1, az1, Xb, Yb, Zb, Hb));
        if (m1 < best1) { best1 = m1; gi1 = g; }
    }

    const float* sf = reinterpret_cast<const float*>(sG);
    const int bi0 = half * NCH + 8 * gi0 + resolve8(sf + 32 * gi0, -rx0, -ry0, -rz0, best0);
    const int bi1 = half * NCH + 8 * gi1 + resolve8(sf + 32 * gi1, -rx1, -ry1, -rz1, best1);

    ull* __restrict__ key = ((ITER == 1) ? g_key1 : g_key2) + (size_t)half * NBATCH * NPTS;
    key[b * NPTS + p0] = make_key(best0, bi0);
    key[b * NPTS + p1] = make_key(best1, bi1);

    if (half == 0) {
        float* __restrict__ p2o = (ITER == 1) ? g_p21 : g_p22;
        p2o[b * NPTS + p0] = rx0 * rx0 + ry0 * ry0 + rz0 * rz0;
        p2o[b * NPTS + p1] = rx1 * rx1 + ry1 * ry1 + rz1 * rz1;
    }
}

// Merge the two half-keys per point, recover min_dist, per-block max.
template <int SET>
__global__ __launch_bounds__(NTHREADS)
void merge_kernel() {
    __shared__ float s_warpmax[NTHREADS / 32];

    const ull* __restrict__ key = (SET == 1) ? g_key1 : g_key2;
    const float* __restrict__ p2 = (SET == 1) ? g_p21 : g_p22;
    float* __restrict__ md = (SET == 1) ? g_md1 : g_md2;
    int*   __restrict__ bi = (SET == 1) ? g_bi1 : g_bi2;
    float* __restrict__ bm = (SET == 1) ? g_bm1 : g_bm2;

    const int i = blockIdx.x * NTHREADS + threadIdx.x;   // global point index
    ull k0 = key[i];
    ull k1 = key[NBATCH * NPTS + i];
    ull k = (k1 < k0) ? k1 : k0;

    const float s = key_score(k);
    const float d = sqrtf(fmaxf(fmaf(2.0f, s, p2[i]), 0.0f));
    md[i] = d;
    bi[i] = (int)(k & 0xffffffffu);

    float m = d;
#pragma unroll
    for (int off = 16; off > 0; off >>= 1)
        m = fmaxf(m, __shfl_xor_sync(0xffffffffu, m, off));
    if ((threadIdx.x & 31) == 0) s_warpmax[threadIdx.x >> 5] = m;
    __syncthreads();
    if (threadIdx.x == 0) {
        float mm = s_warpmax[0];
#pragma unroll
        for (int w = 1; w < NTHREADS / 32; w++) mm = fmaxf(mm, s_warpmax[w]);
        bm[blockIdx.x] = mm;   // blockIdx.x == b * MBLK + (batch-local block)
    }
}

// Replays update 1 (pred -> refined1) and update 2 (refined1 -> out).
__global__ void finalize_kernel(const float* __restrict__ pred,
                                const float* __restrict__ partial,
                                float* __restrict__ out) {
    const int i = blockIdx.x * blockDim.x + threadIdx.x;  // global point index
    if (i >= NBATCH * NPTS) return;
    const int b = i / NPTS;
    const float* __restrict__ pp = partial + (size_t)b * NCAND * 3;

    const float rbm1 = 1.0f / (batch_max(g_bm1, b) + EPS_F);
    const float rbm2 = 1.0f / (batch_max(g_bm2, b) + EPS_F);

    float rx = pred[3 * i], ry = pred[3 * i + 1], rz = pred[3 * i + 2];
    {
        float a = BASE_ALPHA * (2.0f - g_md1[i] * rbm1);
        const float* pc = pp + 3 * g_bi1[i];
        rx += a * (pc[0] - rx); ry += a * (pc[1] - ry); rz += a * (pc[2] - rz);
    }
    {
        float a = BASE_ALPHA * (2.0f - g_md2[i] * rbm2);
        const float* pc = pp + 3 * g_bi2[i];
        rx += a * (pc[0] - rx); ry += a * (pc[1] - ry); rz += a * (pc[2] - rz);
    }
    out[3 * i + 0] = rx;
    out[3 * i + 1] = ry;
    out[3 * i + 2] = rz;
}

extern "C" void kernel_launch(void* const* d_in, const int* in_sizes, int n_in,
                              void* d_out, int out_size) {
    const float* pred    = (const float*)d_in[0];   // [8,8192,3]
    const float* partial = (const float*)d_in[1];   // [8,2048,3]
    float* out = (float*)d_out;                     // [8,8192,3]

    const dim3 ngrid(NHALF * HBLK, NBATCH);         // 256 blocks, 16 warps/SM
    const int mgrid = NBATCH * MBLK;                // 256 merge blocks
    const int tot = NBATCH * NPTS;

    nearest_kernel<1><<<ngrid, NTHREADS>>>(pred, partial);
    merge_kernel<1><<<mgrid, NTHREADS>>>();
    nearest_kernel<2><<<ngrid, NTHREADS>>>(pred, partial);
    merge_kernel<2><<<mgrid, NTHREADS>>>();
    finalize_kernel<<<(tot + 255) / 256, 256>>>(pred, partial, out);
}